// round 2
// baseline (speedup 1.0000x reference)
#include <cuda_runtime.h>
#include <cuda_bf16.h>

// y = x @ (A@B)^T + bias, computed as T = x@B^T (32x64), y = T@A^T + bias.
// x: [32,8192] f32, A: [8192,64] f32, B: [64,8192] f32, bias: [8192] f32.
// out: [32,8192] f32.

#define BATCH 32
#define IN_F  8192
#define OUT_F 8192
#define RANK  64

// Intermediate T[32][64] scratch (device global: no allocation allowed).
__device__ float g_T[BATCH * RANK];

// ---------------------------------------------------------------------------
// Kernel 0: zero the accumulator scratch (graph replays re-run this).
// ---------------------------------------------------------------------------
__global__ void zero_T_kernel() {
    int i = blockIdx.x * blockDim.x + threadIdx.x;
    if (i < BATCH * RANK) g_T[i] = 0.0f;
}

// ---------------------------------------------------------------------------
// Kernel 1: split-K  T[b][r] += sum_{k in chunk} x[b][k] * B[r][k]
// grid = 128 blocks (K chunks of 64), 256 threads.
// smem: x_s[32][68], B_s[64][68] (pad 4 floats -> conflict-free LDS.128)
// thread mapping: r = tid & 63, bgroup = tid >> 6 (8 b's per thread)
// ---------------------------------------------------------------------------
#define S1_CHUNK 64
#define S1_BLOCKS (IN_F / S1_CHUNK)   // 128

__global__ __launch_bounds__(256, 1)
void stage1_kernel(const float* __restrict__ x, const float* __restrict__ Bm) {
    __shared__ float x_s[BATCH][S1_CHUNK + 4];
    __shared__ float B_s[RANK][S1_CHUNK + 4];

    const int tid = threadIdx.x;
    const int k0  = blockIdx.x * S1_CHUNK;

    // Load x chunk: 32 rows x 64 cols = 512 float4
    #pragma unroll
    for (int i = 0; i < 2; i++) {
        int idx = tid + i * 256;                 // 0..511
        int b  = idx >> 4;                       // /16 float4 per row
        int jj = idx & 15;
        float4 v = reinterpret_cast<const float4*>(x + b * IN_F + k0)[jj];
        *reinterpret_cast<float4*>(&x_s[b][jj * 4]) = v;
    }
    // Load B chunk: 64 rows x 64 cols = 1024 float4
    #pragma unroll
    for (int i = 0; i < 4; i++) {
        int idx = tid + i * 256;                 // 0..1023
        int r  = idx >> 4;
        int jj = idx & 15;
        float4 v = reinterpret_cast<const float4*>(Bm + r * IN_F + k0)[jj];
        *reinterpret_cast<float4*>(&B_s[r][jj * 4]) = v;
    }
    __syncthreads();

    const int r  = tid & 63;
    const int b0 = (tid >> 6) * 8;               // 8 batches per thread

    float acc[8];
    #pragma unroll
    for (int j = 0; j < 8; j++) acc[j] = 0.0f;

    #pragma unroll
    for (int k4 = 0; k4 < S1_CHUNK / 4; k4++) {
        float4 bv = *reinterpret_cast<const float4*>(&B_s[r][k4 * 4]);
        #pragma unroll
        for (int j = 0; j < 8; j++) {
            float4 xv = *reinterpret_cast<const float4*>(&x_s[b0 + j][k4 * 4]);
            acc[j] += bv.x * xv.x;
            acc[j] += bv.y * xv.y;
            acc[j] += bv.z * xv.z;
            acc[j] += bv.w * xv.w;
        }
    }

    #pragma unroll
    for (int j = 0; j < 8; j++)
        atomicAdd(&g_T[(b0 + j) * RANK + r], acc[j]);
}

// ---------------------------------------------------------------------------
// Kernel 2: y[b][o] = sum_r T[b][r] * A[o][r] + bias[o]
// grid = 128 blocks (64 outputs each), 256 threads.
// thread mapping: o = tid & 63, bgroup = tid >> 6 (8 b's per thread)
// ---------------------------------------------------------------------------
__global__ __launch_bounds__(256, 1)
void stage2_kernel(const float* __restrict__ A, const float* __restrict__ bias,
                   float* __restrict__ y) {
    __shared__ float A_s[64][RANK + 4];
    __shared__ float T_s[BATCH][RANK + 4];

    const int tid = threadIdx.x;
    const int o0  = blockIdx.x * 64;

    // Load A tile: 64 rows x 64 cols, fully contiguous 16KB -> 1024 float4
    #pragma unroll
    for (int i = 0; i < 4; i++) {
        int idx = tid + i * 256;
        int o  = idx >> 4;
        int jj = idx & 15;
        float4 v = reinterpret_cast<const float4*>(A + (o0 + o) * RANK)[jj];
        *reinterpret_cast<float4*>(&A_s[o][jj * 4]) = v;
    }
    // Load T: 32x64 = 512 float4... actually 2048 floats = 512 float4
    #pragma unroll
    for (int i = 0; i < 2; i++) {
        int idx = tid + i * 256;                 // 0..511
        int b  = idx >> 4;
        int jj = idx & 15;
        float4 v = reinterpret_cast<const float4*>(g_T + b * RANK)[jj];
        *reinterpret_cast<float4*>(&T_s[b][jj * 4]) = v;
    }
    __syncthreads();

    const int o  = tid & 63;
    const int b0 = (tid >> 6) * 8;

    float acc[8];
    #pragma unroll
    for (int j = 0; j < 8; j++) acc[j] = 0.0f;

    #pragma unroll
    for (int r4 = 0; r4 < RANK / 4; r4++) {
        float4 av = *reinterpret_cast<const float4*>(&A_s[o][r4 * 4]);
        #pragma unroll
        for (int j = 0; j < 8; j++) {
            float4 tv = *reinterpret_cast<const float4*>(&T_s[b0 + j][r4 * 4]);
            acc[j] += av.x * tv.x;
            acc[j] += av.y * tv.y;
            acc[j] += av.z * tv.z;
            acc[j] += av.w * tv.w;
        }
    }

    const float bv = bias[o0 + o];
    #pragma unroll
    for (int j = 0; j < 8; j++)
        y[(b0 + j) * OUT_F + o0 + o] = acc[j] + bv;
}

// ---------------------------------------------------------------------------
extern "C" void kernel_launch(void* const* d_in, const int* in_sizes, int n_in,
                              void* d_out, int out_size) {
    const float* x    = (const float*)d_in[0];   // [32, 8192]
    const float* A    = (const float*)d_in[1];   // [8192, 64]
    const float* Bm   = (const float*)d_in[2];   // [64, 8192]
    const float* bias = (const float*)d_in[3];   // [8192]
    float* y = (float*)d_out;                    // [32, 8192]

    zero_T_kernel<<<(BATCH * RANK + 255) / 256, 256>>>();
    stage1_kernel<<<S1_BLOCKS, 256>>>(x, Bm);
    stage2_kernel<<<OUT_F / 64, 256>>>(A, bias, y);
}